// round 4
// baseline (speedup 1.0000x reference)
#include <cuda_runtime.h>

#define NBATCH 16
#define NF     128
#define NT     4096
#define NS     4
#define TPB    256
#define PT     16          // TPB*PT == NT
#define GP     20          // padded group stride (16 data + 4 pad floats)
#define BUFSZ  (TPB * GP)  // 5120 floats = 20KB

typedef unsigned long long u64;

__device__ __forceinline__ float fast_exp2(float x) {
    float r; asm("ex2.approx.ftz.f32 %0, %1;" : "=f"(r) : "f"(x)); return r;
}
__device__ __forceinline__ float fast_log2(float x) {
    float r; asm("lg2.approx.ftz.f32 %0, %1;" : "=f"(r) : "f"(x)); return r;
}

// ---- packed f32x2 helpers (FFMA2/FADD2 path, PTX-only per SASS_QUICKREF) ----
__device__ __forceinline__ u64 pk2(float lo, float hi) {
    u64 d; asm("mov.b64 %0, {%1, %2};" : "=l"(d)
               : "r"(__float_as_uint(lo)), "r"(__float_as_uint(hi)));
    return d;
}
__device__ __forceinline__ void unpk2(u64 v, float& lo, float& hi) {
    unsigned a, b;
    asm("mov.b64 {%0, %1}, %2;" : "=r"(a), "=r"(b) : "l"(v));
    lo = __uint_as_float(a); hi = __uint_as_float(b);
}
__device__ __forceinline__ u64 fma2(u64 a, u64 b, u64 c) {
    u64 d; asm("fma.rn.f32x2 %0, %1, %2, %3;" : "=l"(d) : "l"(a), "l"(b), "l"(c)); return d;
}
__device__ __forceinline__ u64 add2(u64 a, u64 b) {
    u64 d; asm("add.rn.f32x2 %0, %1, %2;" : "=l"(d) : "l"(a), "l"(b)); return d;
}
__device__ __forceinline__ u64 sub2(u64 a, u64 b) {
    u64 d; asm("sub.rn.f32x2 %0, %1, %2;" : "=l"(d) : "l"(a), "l"(b)); return d;
}
__device__ __forceinline__ u64 mul2(u64 a, u64 b) {
    u64 d; asm("mul.rn.f32x2 %0, %1, %2;" : "=l"(d) : "l"(a), "l"(b)); return d;
}

// packed exp2: magic-add range split + deg-5 poly + exponent splice.
// Valid for |t| < 126. magic = 12582912.0f (0x4B400000; low 9 bits zero, so
// bits(2^k * p) == bits(p) + (bits(z) << 23) needs no correction constant).
struct Ex2C {
    u64 magic, c1, c2, c3, c4, c5, one;
};
__device__ __forceinline__ u64 exp2_pk(u64 t, const Ex2C& C) {
    u64 z  = add2(t, C.magic);
    u64 zm = sub2(z, C.magic);
    u64 f  = sub2(t, zm);
    u64 p  = fma2(C.c5, f, C.c4);
    p = fma2(p, f, C.c3);
    p = fma2(p, f, C.c2);
    p = fma2(p, f, C.c1);
    p = fma2(p, f, C.one);
    // splice integer exponent per half
    unsigned z0, z1, p0, p1;
    asm("mov.b64 {%0, %1}, %2;" : "=r"(z0), "=r"(z1) : "l"(z));
    asm("mov.b64 {%0, %1}, %2;" : "=r"(p0), "=r"(p1) : "l"(p));
    unsigned r0 = p0 + (z0 << 23);
    unsigned r1 = p1 + (z1 << 23);
    u64 d; asm("mov.b64 %0, {%1, %2};" : "=l"(d) : "r"(r0), "r"(r1));
    return d;
}

__device__ __forceinline__ int qaddr(int Q) { return (Q >> 2) * GP + (Q & 3) * 4; }

__global__ __launch_bounds__(TPB, 4)
void mrpcen_kernel(const float* __restrict__ x,
                   const float* __restrict__ alpha_log,
                   const float* __restrict__ delta_log,
                   const float* __restrict__ r_log,
                   float* __restrict__ out)
{
    const int row  = blockIdx.x;        // b*NF + f
    const int f    = row & (NF - 1);
    const int b    = row >> 7;
    const int tid  = threadIdx.x;
    const int lane = tid & 31;
    const int w    = tid >> 5;

    __shared__ float buf0[BUFSZ];
    __shared__ float buf1[BUFSZ];
    __shared__ float wagg[NS][TPB / 32];

    // ---- problem-constant smoother coefficients (f32, as in reference) ----
    float s[NS], a[NS], a16[NS];
    {
        const float tv[NS] = {0.015f, 0.06f, 0.25f, 1.0f};
#pragma unroll
        for (int i = 0; i < NS; i++) {
            float tt = tv[i] * (44100.0f / 512.0f);
            float d2 = 2.0f * tt * tt;
            s[i] = (sqrtf(1.0f + 2.0f * d2) - 1.0f) / d2;
            a[i] = 1.0f - s[i];
            float t2 = a[i] * a[i], t4 = t2 * t2, t8 = t4 * t4;
            a16[i] = t8 * t8;
        }
    }

    const float al    = alpha_log[f];
    const float dl    = delta_log[f];
    const float rl    = r_log[f];
    const float alpha = __expf(al);
    const float delta = __expf(dl);
    const float rr    = __expf(rl);
    const float delta_r = __expf(rr * dl);

    // packed constants
    Ex2C C;
    C.magic = pk2(12582912.0f, 12582912.0f);
    C.c1 = pk2(0.69314718056f, 0.69314718056f);
    C.c2 = pk2(0.24022650700f, 0.24022650700f);
    C.c3 = pk2(0.05550410866f, 0.05550410866f);
    C.c4 = pk2(0.00961812911f, 0.00961812911f);
    C.c5 = pk2(0.00133335581f, 0.00133335581f);
    C.one = pk2(1.0f, 1.0f);
    const u64 eps2  = pk2(1e-5f, 1e-5f);
    const u64 nal2  = pk2(-alpha, -alpha);
    const u64 dd2   = pk2(delta, delta);
    const u64 rr2   = pk2(rr, rr);
    const u64 ndr2  = pk2(-delta_r, -delta_r);
    const u64 a01   = pk2(a[0], a[1]);
    const u64 a23   = pk2(a[2], a[3]);
    const u64 s01   = pk2(s[0], s[1]);
    const u64 s23   = pk2(s[2], s[3]);

    // ---- stage x: coalesced LDG.128 -> padded smem ----
    const float* xrow = x + (size_t)row * NT;
#pragma unroll
    for (int j = 0; j < 4; j++) {
        int Q = j * TPB + tid;
        float4 v = *reinterpret_cast<const float4*>(xrow + 4 * Q);
        *reinterpret_cast<float4*>(&buf0[qaddr(Q)]) = v;
    }
    __syncthreads();

    float xv[PT];
#pragma unroll
    for (int q = 0; q < 4; q++) {
        float4 v = *reinterpret_cast<float4*>(&buf0[tid * GP + q * 4]);
        xv[4 * q + 0] = v.x; xv[4 * q + 1] = v.y;
        xv[4 * q + 2] = v.z; xv[4 * q + 3] = v.w;
    }

    // ---- pass 1: packed local recurrences (m_in = 0) ----
    float bc[NS];
    {
        u64 m01 = pk2(0.0f, 0.0f), m23 = m01;
#pragma unroll
        for (int k = 0; k < PT; k++) {
            u64 xkk = pk2(xv[k], xv[k]);
            m01 = fma2(a01, m01, mul2(s01, xkk));
            m23 = fma2(a23, m23, mul2(s23, xkk));
        }
        unpk2(m01, bc[0], bc[1]);
        unpk2(m23, bc[2], bc[3]);
    }
    if (tid == 0) {                      // fold m[0]=x[0] boundary (a+s==1)
#pragma unroll
        for (int si = 0; si < NS; si++) bc[si] = fmaf(a16[si], xv[0], bc[si]);
    }

    // ---- warp-level constant-coefficient inclusive scans (registers) ----
#pragma unroll
    for (int si = 0; si < NS; si++) {
        float c = a16[si];
        float bcar = bc[si];
#pragma unroll
        for (int d = 1; d <= 16; d <<= 1) {
            float up = __shfl_up_sync(0xffffffffu, bcar, d);
            if (lane >= d) bcar = fmaf(c, up, bcar);
            c = c * c;
        }
        bc[si] = bcar;
        if (lane == 31) wagg[si][w] = bcar;
    }
    __syncthreads();

    // ---- cross-warp: segmented 32-lane scan (4 rates x 8 warps) ----
    if (w == 0) {
        const int gsi = lane >> 3, gl = lane & 7;
        float v = wagg[gsi][gl];
        float tt = (gsi == 0) ? (0.015f * (44100.0f / 512.0f)) :
                   (gsi == 1) ? (0.06f  * (44100.0f / 512.0f)) :
                   (gsi == 2) ? (0.25f  * (44100.0f / 512.0f)) :
                                (1.0f   * (44100.0f / 512.0f));
        float d2 = 2.0f * tt * tt;
        float aa = 1.0f - (sqrtf(1.0f + 2.0f * d2) - 1.0f) / d2;
        float c = aa;
#pragma unroll
        for (int i = 0; i < 9; i++) c = c * c;   // a^512
#pragma unroll
        for (int d = 1; d <= 4; d <<= 1) {
            float up = __shfl_up_sync(0xffffffffu, v, d);
            if (gl >= d) v = fmaf(c, up, v);
            c = c * c;
        }
        wagg[gsi][gl] = v;
    }
    __syncthreads();

    // ---- per-thread incoming state per rate ----
    float minv[NS];
#pragma unroll
    for (int si = 0; si < NS; si++) {
        float Lprev = __shfl_up_sync(0xffffffffu, bc[si], 1);
        if (tid == 0) {
            minv[si] = xv[0];
        } else {
            float P = (w > 0) ? wagg[si][w - 1] : 0.0f;
            float a16l = fast_exp2((float)(16 * lane) * fast_log2(a[si]));
            minv[si] = fmaf(a16l, P, (lane > 0) ? Lprev : 0.0f);
        }
    }

    // ---- pass 2: two rate-pair passes, packed math, staged coalesced stores ----
#pragma unroll
    for (int pp = 0; pp < 2; pp++) {
        const u64 aP  = (pp == 0) ? a01 : a23;
        const u64 sP  = (pp == 0) ? s01 : s23;
        u64 mm = (pp == 0) ? pk2(minv[0], minv[1]) : pk2(minv[2], minv[3]);

#pragma unroll
        for (int q = 0; q < 4; q++) {
            float t0[4], t1[4];
#pragma unroll
            for (int e = 0; e < 4; e++) {
                const int k = q * 4 + e;
                u64 xkk = pk2(xv[k], xv[k]);
                mm = fma2(aP, mm, mul2(sP, xkk));
                u64 u = add2(mm, eps2);
                float u0, u1; unpk2(u, u0, u1);
                u64 L  = pk2(fast_log2(u0), fast_log2(u1));
                u64 sm = exp2_pk(mul2(nal2, L), C);        // (eps+m)^-alpha
                u64 v  = fma2(xkk, sm, dd2);               // x*smooth + delta
                float v0, v1; unpk2(v, v0, v1);
                u64 L2 = pk2(fast_log2(v0), fast_log2(v1));
                u64 o  = add2(exp2_pk(mul2(rr2, L2), C), ndr2); // v^r - delta^r
                unpk2(o, t0[e], t1[e]);
            }
            float4 o0, o1;
            o0.x = t0[0]; o0.y = t0[1]; o0.z = t0[2]; o0.w = t0[3];
            o1.x = t1[0]; o1.y = t1[1]; o1.z = t1[2]; o1.w = t1[3];
            *reinterpret_cast<float4*>(&buf0[tid * GP + q * 4]) = o0;
            *reinterpret_cast<float4*>(&buf1[tid * GP + q * 4]) = o1;
        }
        __syncthreads();

        // drain both rates of this pair with coalesced STG.128
#pragma unroll
        for (int h = 0; h < 2; h++) {
            const int si = pp * 2 + h;
            const float* sb = h ? buf1 : buf0;
            float* orow = out + (((size_t)b * NS + si) * NF + f) * (size_t)NT;
#pragma unroll
            for (int j = 0; j < 4; j++) {
                int Q = j * TPB + tid;
                float4 v = *reinterpret_cast<const float4*>(&sb[qaddr(Q)]);
                *reinterpret_cast<float4*>(orow + 4 * Q) = v;
            }
        }
        if (pp == 0) __syncthreads();   // protect bufs before pass B rewrites
    }
}

extern "C" void kernel_launch(void* const* d_in, const int* in_sizes, int n_in,
                              void* d_out, int out_size) {
    const float* x         = (const float*)d_in[0];
    const float* alpha_log = (const float*)d_in[1];
    const float* delta_log = (const float*)d_in[2];
    const float* r_log     = (const float*)d_in[3];
    float* out             = (float*)d_out;
    (void)in_sizes; (void)n_in; (void)out_size;

    dim3 grid(NBATCH * NF);
    dim3 block(TPB);
    mrpcen_kernel<<<grid, block>>>(x, alpha_log, delta_log, r_log, out);
}

// round 5
// speedup vs baseline: 1.4732x; 1.4732x over previous
#include <cuda_runtime.h>

#define NBATCH 16
#define NF     128
#define NT     4096
#define NS     4
#define TPB    256
#define PT     16          // TPB*PT == NT
#define GP     20          // padded group stride (16 data + 4 pad floats)
#define BUFSZ  (TPB * GP)  // 5120 floats = 20KB

__device__ __forceinline__ float fast_exp2(float x) {
    float r; asm("ex2.approx.ftz.f32 %0, %1;" : "=f"(r) : "f"(x)); return r;
}
__device__ __forceinline__ float fast_log2(float x) {
    float r; asm("lg2.approx.ftz.f32 %0, %1;" : "=f"(r) : "f"(x)); return r;
}

// Scalar polynomial exp2: magic-add round + deg-4 poly on f in [-0.5, 0.5]
// + exact exponent splice (low 9 bits of 0x4B400000 are zero, so
// bits(p) + (bits(z) << 23) == bits(p * 2^round(t)) with no correction).
// Valid for |t| < 126; max rel err ~4e-5. All coefficients are immediates.
__device__ __forceinline__ float poly_exp2(float t) {
    const float magic = 12582912.0f;           // 1.5 * 2^23
    float z  = t + magic;
    float zi = z - magic;                      // round(t)
    float f  = t - zi;                         // f in [-0.5, 0.5]
    float p  = fmaf(0.00961812911f, f, 0.05550410866f);
    p = fmaf(p, f, 0.24022650700f);
    p = fmaf(p, f, 0.69314718056f);
    p = fmaf(p, f, 1.0f);
    return __uint_as_float(__float_as_uint(p) + (__float_as_uint(z) << 23));
}

// padded smem float-address of logical element quad Q (elements 4Q..4Q+3)
__device__ __forceinline__ int qaddr(int Q) { return (Q >> 2) * GP + (Q & 3) * 4; }

__global__ __launch_bounds__(TPB, 5)
void mrpcen_kernel(const float* __restrict__ x,
                   const float* __restrict__ alpha_log,
                   const float* __restrict__ delta_log,
                   const float* __restrict__ r_log,
                   float* __restrict__ out)
{
    const int row  = blockIdx.x;        // b*NF + f
    const int f    = row & (NF - 1);
    const int b    = row >> 7;
    const int tid  = threadIdx.x;
    const int lane = tid & 31;
    const int w    = tid >> 5;

    __shared__ float buf[2][BUFSZ];
    __shared__ float wagg[NS][TPB / 32];

    // ---- problem-constant smoother coefficients (f32, as in reference) ----
    float s[NS], a[NS], a16[NS];
    {
        const float tv[NS] = {0.015f, 0.06f, 0.25f, 1.0f};
#pragma unroll
        for (int i = 0; i < NS; i++) {
            float tt = tv[i] * (44100.0f / 512.0f);
            float d2 = 2.0f * tt * tt;
            s[i] = (sqrtf(1.0f + 2.0f * d2) - 1.0f) / d2;
            a[i] = 1.0f - s[i];
            float t2 = a[i] * a[i], t4 = t2 * t2, t8 = t4 * t4;
            a16[i] = t8 * t8;
        }
    }

    const float al    = alpha_log[f];
    const float dl    = delta_log[f];
    const float rl    = r_log[f];
    const float alpha = __expf(al);
    const float delta = __expf(dl);
    const float rr    = __expf(rl);
    const float delta_r = __expf(rr * dl);

    // ---- stage x: coalesced LDG.128 -> padded smem ----
    const float* xrow = x + (size_t)row * NT;
#pragma unroll
    for (int j = 0; j < 4; j++) {
        int Q = j * TPB + tid;
        float4 v = *reinterpret_cast<const float4*>(xrow + 4 * Q);
        *reinterpret_cast<float4*>(&buf[0][qaddr(Q)]) = v;
    }
    __syncthreads();

    // each thread pulls its 16 contiguous elements (own padded group)
    float xv[PT];
#pragma unroll
    for (int q = 0; q < 4; q++) {
        float4 v = *reinterpret_cast<float4*>(&buf[0][tid * GP + q * 4]);
        xv[4 * q + 0] = v.x; xv[4 * q + 1] = v.y;
        xv[4 * q + 2] = v.z; xv[4 * q + 3] = v.w;
    }

    // ---- pass 1 + register scans, all 4 rates ----
    float bc[NS];
#pragma unroll
    for (int si = 0; si < NS; si++) {
        float bcar = 0.0f;
#pragma unroll
        for (int k = 0; k < PT; k++)
            bcar = fmaf(a[si], bcar, s[si] * xv[k]);
        if (tid == 0)                       // fold m[0]=x[0] boundary (a+s==1)
            bcar = fmaf(a16[si], xv[0], bcar);
        float c = a16[si];
#pragma unroll
        for (int d = 1; d <= 16; d <<= 1) {
            float up = __shfl_up_sync(0xffffffffu, bcar, d);
            if (lane >= d) bcar = fmaf(c, up, bcar);
            c = c * c;
        }
        bc[si] = bcar;
        if (lane == 31) wagg[si][w] = bcar;
    }
    __syncthreads();

    // ---- cross-warp: one segmented 32-lane scan handles 4 rates x 8 warps ----
    if (w == 0) {
        const int gsi = lane >> 3, gl = lane & 7;
        float v = wagg[gsi][gl];
        float tt = (gsi == 0) ? (0.015f * (44100.0f / 512.0f)) :
                   (gsi == 1) ? (0.06f  * (44100.0f / 512.0f)) :
                   (gsi == 2) ? (0.25f  * (44100.0f / 512.0f)) :
                                (1.0f   * (44100.0f / 512.0f));
        float d2 = 2.0f * tt * tt;
        float aa = 1.0f - (sqrtf(1.0f + 2.0f * d2) - 1.0f) / d2;
        float c = aa;
#pragma unroll
        for (int i = 0; i < 9; i++) c = c * c;   // a^512
#pragma unroll
        for (int d = 1; d <= 4; d <<= 1) {
            float up = __shfl_up_sync(0xffffffffu, v, d);
            if (gl >= d) v = fmaf(c, up, v);
            c = c * c;
        }
        wagg[gsi][gl] = v;                       // inclusive warp prefix
    }
    __syncthreads();

    // ---- per-thread incoming state for each rate ----
    float minv[NS];
#pragma unroll
    for (int si = 0; si < NS; si++) {
        float Lprev = __shfl_up_sync(0xffffffffu, bc[si], 1);
        if (tid == 0) {
            minv[si] = xv[0];
        } else {
            float P = (w > 0) ? wagg[si][w - 1] : 0.0f;
            float a16l = fast_exp2((float)(16 * lane) * fast_log2(a[si]));
            minv[si] = fmaf(a16l, P, (lane > 0) ? Lprev : 0.0f);
        }
    }

    // ---- pass 2: recurrence + fused PCEN (poly exp2), staged coalesced stores ----
#pragma unroll
    for (int si = 0; si < NS; si++) {
        float m = minv[si];
        float* sb = buf[si & 1];
#pragma unroll
        for (int q = 0; q < 4; q++) {
            float t4[4];
#pragma unroll
            for (int e = 0; e < 4; e++) {
                const int k = q * 4 + e;
                m = fmaf(a[si], m, s[si] * xv[k]);
                const float u  = 1e-5f + m;                         // eps + m
                const float sm = poly_exp2(-alpha * fast_log2(u));  // (eps+m)^-alpha
                const float v2 = fmaf(xv[k], sm, delta);            // x*smooth + delta
                t4[e] = poly_exp2(rr * fast_log2(v2)) - delta_r;    // v^r - delta^r
            }
            float4 o; o.x = t4[0]; o.y = t4[1]; o.z = t4[2]; o.w = t4[3];
            *reinterpret_cast<float4*>(&sb[tid * GP + q * 4]) = o;  // own group
        }
        __syncthreads();
        float* orow = out + (((size_t)b * NS + si) * NF + f) * (size_t)NT;
#pragma unroll
        for (int j = 0; j < 4; j++) {
            int Q = j * TPB + tid;
            float4 v = *reinterpret_cast<float4*>(&sb[qaddr(Q)]);
            *reinterpret_cast<float4*>(orow + 4 * Q) = v;           // coalesced STG.128
        }
        // double-buffered: next rate writes the other buffer; the next rate's
        // barrier orders this rate's reads before buffer reuse two rates later
    }
}

extern "C" void kernel_launch(void* const* d_in, const int* in_sizes, int n_in,
                              void* d_out, int out_size) {
    const float* x         = (const float*)d_in[0];
    const float* alpha_log = (const float*)d_in[1];
    const float* delta_log = (const float*)d_in[2];
    const float* r_log     = (const float*)d_in[3];
    float* out             = (float*)d_out;
    (void)in_sizes; (void)n_in; (void)out_size;

    dim3 grid(NBATCH * NF);   // 2048 blocks: one per (b, f) row
    dim3 block(TPB);
    mrpcen_kernel<<<grid, block>>>(x, alpha_log, delta_log, r_log, out);
}

// round 6
// speedup vs baseline: 1.5556x; 1.0559x over previous
#include <cuda_runtime.h>

#define NBATCH 16
#define NF     128
#define NT     4096
#define NS     4
#define TPB    512
#define PT     8           // TPB*PT == NT
#define GP     12          // padded group stride (8 data + 4 pad floats)
#define BUFSZ  (TPB * GP)  // 6144 floats = 24KB

__device__ __forceinline__ float fast_exp2(float x) {
    float r; asm("ex2.approx.ftz.f32 %0, %1;" : "=f"(r) : "f"(x)); return r;
}
__device__ __forceinline__ float fast_log2(float x) {
    float r; asm("lg2.approx.ftz.f32 %0, %1;" : "=f"(r) : "f"(x)); return r;
}

// padded smem float-address of logical quad Q (elements 4Q..4Q+3); group = 2 quads
__device__ __forceinline__ int qaddr(int Q) { return (Q >> 1) * GP + (Q & 1) * 4; }

__global__ __launch_bounds__(TPB, 3)
void mrpcen_kernel(const float* __restrict__ x,
                   const float* __restrict__ alpha_log,
                   const float* __restrict__ delta_log,
                   const float* __restrict__ r_log,
                   float* __restrict__ out)
{
    const int row  = blockIdx.x;        // b*NF + f
    const int f    = row & (NF - 1);
    const int b    = row >> 7;
    const int tid  = threadIdx.x;
    const int lane = tid & 31;
    const int w    = tid >> 5;          // 16 warps

    __shared__ float buf[2][BUFSZ];
    __shared__ float wagg[NS][TPB / 32];

    // ---- problem-constant smoother coefficients (f32, as in reference) ----
    float s[NS], a[NS], a8[NS];
    {
        const float tv[NS] = {0.015f, 0.06f, 0.25f, 1.0f};
#pragma unroll
        for (int i = 0; i < NS; i++) {
            float tt = tv[i] * (44100.0f / 512.0f);
            float d2 = 2.0f * tt * tt;
            s[i] = (sqrtf(1.0f + 2.0f * d2) - 1.0f) / d2;
            a[i] = 1.0f - s[i];
            float t2 = a[i] * a[i], t4 = t2 * t2;
            a8[i] = t4 * t4;
        }
    }

    const float al    = alpha_log[f];
    const float dl    = delta_log[f];
    const float rl    = r_log[f];
    const float alpha = __expf(al);
    const float delta = __expf(dl);
    const float rr    = __expf(rl);
    const float delta_r = __expf(rr * dl);

    // ---- stage x: coalesced LDG.128 -> padded smem ----
    const float* xrow = x + (size_t)row * NT;
#pragma unroll
    for (int j = 0; j < 2; j++) {
        int Q = j * TPB + tid;
        float4 v = *reinterpret_cast<const float4*>(xrow + 4 * Q);
        *reinterpret_cast<float4*>(&buf[0][qaddr(Q)]) = v;
    }
    __syncthreads();

    // each thread pulls its 8 contiguous elements (own padded group)
    float xv[PT];
#pragma unroll
    for (int q = 0; q < 2; q++) {
        float4 v = *reinterpret_cast<float4*>(&buf[0][tid * GP + q * 4]);
        xv[4 * q + 0] = v.x; xv[4 * q + 1] = v.y;
        xv[4 * q + 2] = v.z; xv[4 * q + 3] = v.w;
    }

    // ---- pass 1 + warp register scans, all 4 rates ----
    float bc[NS];
#pragma unroll
    for (int si = 0; si < NS; si++) {
        float bcar = 0.0f;
#pragma unroll
        for (int k = 0; k < PT; k++)
            bcar = fmaf(a[si], bcar, s[si] * xv[k]);
        if (tid == 0)                       // fold m[0]=x[0] boundary (a+s==1)
            bcar = fmaf(a8[si], xv[0], bcar);
        float c = a8[si];
#pragma unroll
        for (int d = 1; d <= 16; d <<= 1) {
            float up = __shfl_up_sync(0xffffffffu, bcar, d);
            if (lane >= d) bcar = fmaf(c, up, bcar);
            c = c * c;
        }
        bc[si] = bcar;
        if (lane == 31) wagg[si][w] = bcar;
    }
    __syncthreads();

    // ---- cross-warp: warps 0,1 scan 4 rates x 16 warp-aggregates (segmented) ----
    if (w < 2) {
        const int gsi = 2 * w + (lane >> 4);   // rate handled by this half-warp
        const int gl  = lane & 15;
        float v = wagg[gsi][gl];
        float tt = (gsi == 0) ? (0.015f * (44100.0f / 512.0f)) :
                   (gsi == 1) ? (0.06f  * (44100.0f / 512.0f)) :
                   (gsi == 2) ? (0.25f  * (44100.0f / 512.0f)) :
                                (1.0f   * (44100.0f / 512.0f));
        float d2 = 2.0f * tt * tt;
        float aa = 1.0f - (sqrtf(1.0f + 2.0f * d2) - 1.0f) / d2;
        float c = aa;
#pragma unroll
        for (int i = 0; i < 8; i++) c = c * c;   // a^256 = a^(8*32)
#pragma unroll
        for (int d = 1; d <= 8; d <<= 1) {
            float up = __shfl_up_sync(0xffffffffu, v, d);
            if (gl >= d) v = fmaf(c, up, v);
            c = c * c;
        }
        wagg[gsi][gl] = v;                       // inclusive warp prefix
    }
    __syncthreads();

    // ---- per-thread incoming state per rate ----
    float minv[NS];
#pragma unroll
    for (int si = 0; si < NS; si++) {
        float Lprev = __shfl_up_sync(0xffffffffu, bc[si], 1);
        if (tid == 0) {
            minv[si] = xv[0];
        } else {
            float P = (w > 0) ? wagg[si][w - 1] : 0.0f;
            float a8l = fast_exp2((float)(8 * lane) * fast_log2(a[si]));
            minv[si] = fmaf(a8l, P, (lane > 0) ? Lprev : 0.0f);
        }
    }

    // ---- pass 2: recurrence + fused PCEN, double-buffered coalesced stores ----
#pragma unroll
    for (int si = 0; si < NS; si++) {
        float m = minv[si];
        float* sb = buf[si & 1];
#pragma unroll
        for (int q = 0; q < 2; q++) {
            float t4[4];
#pragma unroll
            for (int e = 0; e < 4; e++) {
                const int k = q * 4 + e;
                m = fmaf(a[si], m, s[si] * xv[k]);
                const float u  = 1e-5f + m;                         // eps + m
                const float sm = fast_exp2(-alpha * fast_log2(u));  // (eps+m)^-alpha
                const float v2 = fmaf(xv[k], sm, delta);            // x*smooth + delta
                t4[e] = fast_exp2(rr * fast_log2(v2)) - delta_r;    // v^r - delta^r
            }
            float4 o; o.x = t4[0]; o.y = t4[1]; o.z = t4[2]; o.w = t4[3];
            *reinterpret_cast<float4*>(&sb[tid * GP + q * 4]) = o;  // own group
        }
        __syncthreads();
        float* orow = out + (((size_t)b * NS + si) * NF + f) * (size_t)NT;
#pragma unroll
        for (int j = 0; j < 2; j++) {
            int Q = j * TPB + tid;
            float4 v = *reinterpret_cast<float4*>(&sb[qaddr(Q)]);
            *reinterpret_cast<float4*>(orow + 4 * Q) = v;           // coalesced STG.128
        }
        // double-buffered: the sync at the top of rate si+1 orders this drain
        // before buffer reuse two rates later
    }
}

extern "C" void kernel_launch(void* const* d_in, const int* in_sizes, int n_in,
                              void* d_out, int out_size) {
    const float* x         = (const float*)d_in[0];
    const float* alpha_log = (const float*)d_in[1];
    const float* delta_log = (const float*)d_in[2];
    const float* r_log     = (const float*)d_in[3];
    float* out             = (float*)d_out;
    (void)in_sizes; (void)n_in; (void)out_size;

    dim3 grid(NBATCH * NF);   // 2048 blocks: one per (b, f) row
    dim3 block(TPB);
    mrpcen_kernel<<<grid, block>>>(x, alpha_log, delta_log, r_log, out);
}